// round 17
// baseline (speedup 1.0000x reference)
#include <cuda_runtime.h>
#include <cstdint>

// Max-unpool scatter, deterministic last-index-wins (matches reference).
//
// Round-17: champion (R16, 129.8us) with ONE change — compact at 16
// outputs/thread using LINEAR addressing (4 consecutive uint4 reads per
// thread, preserving the L1 reuse that R6's block-strided 16/thread broke).
// Doubles the per-thread x-gather MLP in the latency-bound compact phase.
//   Z: zero scratch, 4x consecutive uint4/thread (champion exact)
//   S: atomicMax(scr[pos[i]], i+1), 8 atomics/thread, pos __ldcs (exact)
//   C: linear 16/thread; scratch __ldcs, x __ldg, out __stcs

#define N_OUT_CONST 25690112  // 32*112*112*64

__device__ unsigned int g_winner[N_OUT_CONST];

// count16 = N_OUT/16 threads, each writes 4 consecutive uint4 (64B).
__global__ void zero_scratch_kernel(int count16) {
    int t = blockIdx.x * blockDim.x + threadIdx.x;
    if (t < count16) {
        uint4* p = reinterpret_cast<uint4*>(g_winner) + 4 * t;
        uint4 z = make_uint4(0u, 0u, 0u, 0u);
        p[0] = z; p[1] = z; p[2] = z; p[3] = z;
    }
}

// n8 = n/8 threads, each loads 2 int4 of pos and issues 8 atomics.
__global__ void scatter_kernel(const int4* __restrict__ p4, int n8) {
    int t = blockIdx.x * blockDim.x + threadIdx.x;
    if (t >= n8) return;
    int4 a = __ldcs(&p4[2 * t + 0]);
    int4 b = __ldcs(&p4[2 * t + 1]);
    unsigned int base = (unsigned int)(t * 8);
    atomicMax(&g_winner[a.x], base + 1u);
    atomicMax(&g_winner[a.y], base + 2u);
    atomicMax(&g_winner[a.z], base + 3u);
    atomicMax(&g_winner[a.w], base + 4u);
    atomicMax(&g_winner[b.x], base + 5u);
    atomicMax(&g_winner[b.y], base + 6u);
    atomicMax(&g_winner[b.z], base + 7u);
    atomicMax(&g_winner[b.w], base + 8u);
}

// count16 threads, each consumes 4 CONSECUTIVE uint4 slots (64B) and
// produces 16 outputs: all 16 gathers issued before any store.
__global__ void compact_kernel(float* __restrict__ out,
                               const float* __restrict__ x,
                               int count16) {
    int t = blockIdx.x * blockDim.x + threadIdx.x;
    if (t >= count16) return;

    const uint4* __restrict__ sp = reinterpret_cast<const uint4*>(g_winner);
    float4* __restrict__ op = reinterpret_cast<float4*>(out);

    uint4 w[4];
#pragma unroll
    for (int k = 0; k < 4; k++) w[k] = __ldcs(&sp[4 * t + k]);

    float4 o[4];
#pragma unroll
    for (int k = 0; k < 4; k++) {
        o[k].x = w[k].x ? __ldg(&x[w[k].x - 1u]) : 0.0f;
        o[k].y = w[k].y ? __ldg(&x[w[k].y - 1u]) : 0.0f;
        o[k].z = w[k].z ? __ldg(&x[w[k].z - 1u]) : 0.0f;
        o[k].w = w[k].w ? __ldg(&x[w[k].w - 1u]) : 0.0f;
    }

#pragma unroll
    for (int k = 0; k < 4; k++) __stcs(&op[4 * t + k], o[k]);
}

extern "C" void kernel_launch(void* const* d_in, const int* in_sizes, int n_in,
                              void* d_out, int out_size) {
    const float* x = reinterpret_cast<const float*>(d_in[0]);
    const int* pos = reinterpret_cast<const int*>(d_in[1]);
    float* out     = reinterpret_cast<float*>(d_out);

    int n = in_sizes[0];             // 6,422,528 (divisible by 8)
    int n8 = n / 8;
    int count16 = out_size / 16;     // 1,605,632

    const int T = 256;

    // Z: zero the winner scratch (heats it in L2 right before the atomics).
    zero_scratch_kernel<<<(count16 + T - 1) / T, T>>>(count16);

    // S: deterministic last-index-wins via 32-bit atomicMax, 8/thread.
    scatter_kernel<<<(n8 + T - 1) / T, T>>>(
        reinterpret_cast<const int4*>(pos), n8);

    // C: gather winners' values, zero-fill empties, stream out, 16/thread.
    compact_kernel<<<(count16 + T - 1) / T, T>>>(out, x, count16);
}